// round 11
// baseline (speedup 1.0000x reference)
#include <cuda_runtime.h>

#define NN 52      // nodes
#define NE 832     // edges
#define E2 884     // edges + self loops
#define FD 256     // feature dim
#define NT 256     // threads per CTA (2 CTAs/SM)

union F2U { float2 f; unsigned long long u; };

__device__ __forceinline__ unsigned long long pack2(float a, float b){
    F2U t; t.f = make_float2(a, b); return t.u;
}
__device__ __forceinline__ float2 unpack2(unsigned long long v){
    F2U t; t.u = v; return t.f;
}
// packed dual-fp32 FMA (sm_100+)
__device__ __forceinline__ void fma2(unsigned long long& d,
                                     unsigned long long a,
                                     unsigned long long b){
    asm("fma.rn.f32x2 %0, %1, %2, %0;" : "+l"(d) : "l"(a), "l"(b));
}
__device__ __forceinline__ float sigmoidf_(float x){
    return 1.f / (1.f + __expf(-x));
}

// paired-row address: element (r, k) of the activation tile
__device__ __forceinline__ int paddr(int r, int k){
    return (r >> 1)*2*FD + 2*k + (r & 1);
}

// shared memory: sA(paired) + sB + alpha + src16 + as/ad + small + off
constexpr int SM_WORDS = NN*FD + NN*FD + E2 + (E2+1)/2 + FD*2 + NN*5 + (NN+1);
constexpr int SMEM_BYTES = SM_WORDS * 4;

__global__ void __launch_bounds__(NT, 2)
gcab_kernel(const float* __restrict__ xg, const void* __restrict__ eig,
            const float* __restrict__ W0, const float* __restrict__ as0,
            const float* __restrict__ ad0, const float* __restrict__ b0,
            const float* __restrict__ W1, const float* __restrict__ as1,
            const float* __restrict__ ad1, const float* __restrict__ b1,
            const float* __restrict__ Wm, const float* __restrict__ bm,
            const float* __restrict__ wgp, const float* __restrict__ bgp,
            float* __restrict__ outg)
{
    extern __shared__ float sm[];
    float* sA    = sm;                 // [26 pairs][512] paired-row activations
    float* sB    = sA + NN*FD;         // [52][256] xp row-major (+ overlays)
    float* sAlpha= sB + NN*FD;         // [884] edge alpha
    short* sSrc  = (short*)(sAlpha + E2);        // [884] src (int16)
    float* sAs   = sAlpha + E2 + (E2+1)/2;       // [256]
    float* sAd   = sAs + FD;           // [256]
    float* sAsrc = sAd + FD;           // [52]
    float* sAdst = sAsrc + NN;         // [52]
    float* sHmax = sAdst + NN;         // [52]
    float* sDinv = sHmax + NN;         // [52]
    float* sMno  = sDinv + NN;         // [52]
    int*   sOff  = (int*)(sMno + NN);  // [53]
    // setup-phase overlays inside sB
    int*   sS    = (int*)sB;           // [884]
    int*   sD    = sS + E2;            // [884]
    int*   sCnt  = sD + E2;            // [52]
    // epilogue-phase overlays inside sB
    float* sAvg  = sB;                 // [256]
    float* sMx   = sB + FD;            // [256]
    float* sMch  = sB + 2*FD;          // [256]
    __shared__ int sIs64;

    const int tid  = threadIdx.x;
    const int g    = blockIdx.x;
    const int lane = tid & 31, wrp = tid >> 5;

    // ------- detect edge_index dtype (int64 vs int32) -------
    if (tid == 0){
        const int* e32 = (const int*)eig;
        int flag = 1;
        #pragma unroll 1
        for (int i = 0; i < 32; i++){
            if (e32[2*i + 1] != 0){ flag = 0; break; }
        }
        sIs64 = flag;
    }

    // ---------------- load x into paired layout ----------------
    {
        const float* xr = xg + (size_t)g*NN*FD;
        for (int i = tid; i < NN*FD; i += NT){
            int r = i >> 8;
            int f = i & 255;
            sA[paddr(r, f)] = xr[i];
        }
        if (tid < NN) sCnt[tid] = 0;
    }
    __syncthreads();

    // ---------------- load edges (into sB overlay) ----------------
    {
        const int is64 = sIs64;
        const long long* ei64 = (const long long*)eig + (size_t)g*2*NE;
        const int*       ei32 = (const int*)eig       + (size_t)g*2*NE;
        for (int e = tid; e < E2; e += NT){
            int s, d;
            if (e < NE){
                if (is64){ s = (int)ei64[e]; d = (int)ei64[NE + e]; }
                else     { s = ei32[e];      d = ei32[NE + e]; }
            } else {
                s = e - NE; d = e - NE;
            }
            sS[e] = s; sD[e] = d;
        }
    }
    __syncthreads();
    for (int e = tid; e < E2; e += NT) atomicAdd(&sCnt[sD[e]], 1);
    __syncthreads();
    if (tid == 0){
        int acc = 0;
        for (int i = 0; i < NN; i++){ sOff[i] = acc; acc += sCnt[i]; }
        sOff[NN] = acc;
    }
    if (tid >= 32 && tid < 32 + NN) sDinv[tid-32] = rsqrtf((float)sCnt[tid-32]);
    __syncthreads();
    // deterministic CSR fill: 7 nodes per warp (8 warps), writes int16 src
    {
        int nds[7], poss[7];
#pragma unroll
        for (int j = 0; j < 7; j++){
            nds[j]  = wrp + 8*j;
            poss[j] = (nds[j] < NN) ? sOff[nds[j]] : 0;
        }
        const unsigned lt = (1u << lane) - 1u;
        for (int base = 0; base < E2; base += 32){
            int e = base + lane;
            int d = -1, s = 0;
            if (e < E2){ d = sD[e]; s = sS[e]; }
#pragma unroll
            for (int j = 0; j < 7; j++){
                unsigned m = __ballot_sync(0xffffffffu, d == nds[j]);
                if (d == nds[j]) sSrc[poss[j] + __popc(m & lt)] = (short)s;
                poss[j] += __popc(m);
            }
        }
    }
    __syncthreads();

    // GEMM thread mapping: 64 col-quads x 4 row-groups of 13 rows
    const int colq = tid & 63;       // cols 4*colq .. 4*colq+3
    const int rq   = tid >> 6;       // rows rq*13 .. rq*13+12
    const int rbase = rq*13;
    // row group = 6 even-odd pairs + 1 scalar row
    const int pstart = (rbase & 1) ? rbase + 1  : rbase;       // even
    const int srow   = (rbase & 1) ? rbase      : rbase + 12;
    const int sodd   = srow & 1;

    // ---------------- two GAT rounds ----------------
    for (int rnd = 0; rnd < 2; rnd++){
        const float* W  = rnd ? W1  : W0;
        const float* av = rnd ? as1 : as0;
        const float* dv = rnd ? ad1 : ad0;
        const float* bb = rnd ? b1  : b0;
        for (int i = tid; i < FD; i += NT){ sAs[i] = av[i]; sAd[i] = dv[i]; }
        __syncthreads();   // sB (epilogue overlay / old xp) reuse barrier

        // GEMM: sB[52][256] = A[52][256] @ W[256][256]
        // thread tile: 13 rows x 4 cols; x loaded as k-pair LDS.128
        {
            unsigned long long accp[6][4];   // row-pairs x 4 cols (lanes=rows)
            unsigned long long accs[2];      // scalar row, cols packed
#pragma unroll
            for (int i = 0; i < 6; i++)
#pragma unroll
                for (int c = 0; c < 4; c++) accp[i][c] = 0ull;
            accs[0] = accs[1] = 0ull;

            const float* wb0 = W + 4*colq;
            const float4* xp4 = reinterpret_cast<const float4*>(sA + (pstart >> 1)*2*FD);
            const float4* xs4 = reinterpret_cast<const float4*>(sA + (srow >> 1)*2*FD);

            float4 wA[4], wB[4];
#pragma unroll
            for (int j = 0; j < 4; j++)
                wA[j] = *reinterpret_cast<const float4*>(wb0 + (size_t)j*FD);

#pragma unroll 1
            for (int kb = 0; kb < 256; kb += 8){
                // prefetch W bank B: k = kb+4 .. kb+7
#pragma unroll
                for (int j = 0; j < 4; j++)
                    wB[j] = *reinterpret_cast<const float4*>(wb0 + (size_t)(kb+4+j)*FD);
                // process bank A: k-pairs (kb+2jp, kb+2jp+1)
#pragma unroll
                for (int jp = 0; jp < 2; jp++){
                    const int k0 = kb + 2*jp;
                    float4 w0 = wA[2*jp];       // W row k0, 4 cols
                    float4 w1 = wA[2*jp+1];     // W row k0+1
                    unsigned long long w0s[4], w1s[4];
                    w0s[0] = pack2(w0.x, w0.x); w0s[1] = pack2(w0.y, w0.y);
                    w0s[2] = pack2(w0.z, w0.z); w0s[3] = pack2(w0.w, w0.w);
                    w1s[0] = pack2(w1.x, w1.x); w1s[1] = pack2(w1.y, w1.y);
                    w1s[2] = pack2(w1.z, w1.z); w1s[3] = pack2(w1.w, w1.w);
#pragma unroll
                    for (int i = 0; i < 6; i++){
                        float4 xv = xp4[i*128 + (k0 >> 1)];   // rows pair, k0 & k0+1
                        F2U lo; lo.f = make_float2(xv.x, xv.y);
                        F2U hi; hi.f = make_float2(xv.z, xv.w);
#pragma unroll
                        for (int c = 0; c < 4; c++) fma2(accp[i][c], lo.u, w0s[c]);
#pragma unroll
                        for (int c = 0; c < 4; c++) fma2(accp[i][c], hi.u, w1s[c]);
                    }
                    {
                        float4 sv = xs4[k0 >> 1];
                        float xa = sodd ? sv.y : sv.x;   // scalar row, k0
                        float xb = sodd ? sv.w : sv.z;   // scalar row, k0+1
                        unsigned long long xda = pack2(xa, xa);
                        unsigned long long xdb = pack2(xb, xb);
                        F2U p00; p00.f = make_float2(w0.x, w0.y);
                        F2U p01; p01.f = make_float2(w0.z, w0.w);
                        F2U p10; p10.f = make_float2(w1.x, w1.y);
                        F2U p11; p11.f = make_float2(w1.z, w1.w);
                        fma2(accs[0], xda, p00.u);
                        fma2(accs[1], xda, p01.u);
                        fma2(accs[0], xdb, p10.u);
                        fma2(accs[1], xdb, p11.u);
                    }
                }
                // prefetch W bank A: k = kb+8 .. kb+11 (clamped)
                {
                    int kn = (kb + 8 < 256) ? (kb + 8) : 0;
#pragma unroll
                    for (int j = 0; j < 4; j++)
                        wA[j] = *reinterpret_cast<const float4*>(wb0 + (size_t)(kn+j)*FD);
                }
                // process bank B: k-pairs (kb+4+2jp, kb+5+2jp)
#pragma unroll
                for (int jp = 0; jp < 2; jp++){
                    const int k0 = kb + 4 + 2*jp;
                    float4 w0 = wB[2*jp];
                    float4 w1 = wB[2*jp+1];
                    unsigned long long w0s[4], w1s[4];
                    w0s[0] = pack2(w0.x, w0.x); w0s[1] = pack2(w0.y, w0.y);
                    w0s[2] = pack2(w0.z, w0.z); w0s[3] = pack2(w0.w, w0.w);
                    w1s[0] = pack2(w1.x, w1.x); w1s[1] = pack2(w1.y, w1.y);
                    w1s[2] = pack2(w1.z, w1.z); w1s[3] = pack2(w1.w, w1.w);
#pragma unroll
                    for (int i = 0; i < 6; i++){
                        float4 xv = xp4[i*128 + (k0 >> 1)];
                        F2U lo; lo.f = make_float2(xv.x, xv.y);
                        F2U hi; hi.f = make_float2(xv.z, xv.w);
#pragma unroll
                        for (int c = 0; c < 4; c++) fma2(accp[i][c], lo.u, w0s[c]);
#pragma unroll
                        for (int c = 0; c < 4; c++) fma2(accp[i][c], hi.u, w1s[c]);
                    }
                    {
                        float4 sv = xs4[k0 >> 1];
                        float xa = sodd ? sv.y : sv.x;
                        float xb = sodd ? sv.w : sv.z;
                        unsigned long long xda = pack2(xa, xa);
                        unsigned long long xdb = pack2(xb, xb);
                        F2U p00; p00.f = make_float2(w0.x, w0.y);
                        F2U p01; p01.f = make_float2(w0.z, w0.w);
                        F2U p10; p10.f = make_float2(w1.x, w1.y);
                        F2U p11; p11.f = make_float2(w1.z, w1.w);
                        fma2(accs[0], xda, p00.u);
                        fma2(accs[1], xda, p01.u);
                        fma2(accs[0], xdb, p10.u);
                        fma2(accs[1], xdb, p11.u);
                    }
                }
            }
            // store: pair rows as float4 (cols 4colq..+3)
#pragma unroll
            for (int i = 0; i < 6; i++){
                float2 c0 = unpack2(accp[i][0]);
                float2 c1 = unpack2(accp[i][1]);
                float2 c2 = unpack2(accp[i][2]);
                float2 c3 = unpack2(accp[i][3]);
                int r0 = pstart + 2*i;
                reinterpret_cast<float4*>(sB + r0*FD)[colq] =
                    make_float4(c0.x, c1.x, c2.x, c3.x);
                reinterpret_cast<float4*>(sB + (r0+1)*FD)[colq] =
                    make_float4(c0.y, c1.y, c2.y, c3.y);
            }
            {
                float2 a0 = unpack2(accs[0]);
                float2 a1 = unpack2(accs[1]);
                reinterpret_cast<float4*>(sB + srow*FD)[colq] =
                    make_float4(a0.x, a0.y, a1.x, a1.y);
            }
        }
        __syncthreads();

        // asrc/adst per row: warp-per-row, a_s/a_d cached in regs, packed fma2
        {
            const float2* sAs2 = reinterpret_cast<const float2*>(sAs);
            const float2* sAd2 = reinterpret_cast<const float2*>(sAd);
            F2U avr[4], dvr[4];
#pragma unroll
            for (int t = 0; t < 4; t++){
                avr[t].f = sAs2[lane + 32*t];
                dvr[t].f = sAd2[lane + 32*t];
            }
            for (int r = wrp; r < NN; r += 8){
                const float2* vb = reinterpret_cast<const float2*>(sB + r*FD);
                unsigned long long sa2 = 0ull, sd2 = 0ull;
#pragma unroll
                for (int t = 0; t < 4; t++){
                    F2U v; v.f = vb[lane + 32*t];
                    fma2(sa2, v.u, avr[t].u);
                    fma2(sd2, v.u, dvr[t].u);
                }
                float2 sap = unpack2(sa2), sdp = unpack2(sd2);
                float sa = sap.x + sap.y, sd = sdp.x + sdp.y;
#pragma unroll
                for (int o = 16; o; o >>= 1){
                    sa += __shfl_down_sync(0xffffffffu, sa, o);
                    sd += __shfl_down_sync(0xffffffffu, sd, o);
                }
                if (lane == 0){ sAsrc[r] = sa; sAdst[r] = sd; }
            }
        }
        __syncthreads();

        // fused logits + per-dest softmax: warp per node
        for (int nd = wrp; nd < NN; nd += 8){
            int beg = sOff[nd], end = sOff[nd+1];
            float adn = sAdst[nd];
            float m = -3.0e38f;
            for (int t = beg + lane; t < end; t += 32){
                int src = sSrc[t];
                float el = sAsrc[src] + adn;
                el = el > 0.f ? el : 0.2f * el;
                sAlpha[t] = el;
                m = fmaxf(m, el);
            }
#pragma unroll
            for (int o = 16; o; o >>= 1)
                m = fmaxf(m, __shfl_xor_sync(0xffffffffu, m, o));
            float s = 0.f;
            for (int t = beg + lane; t < end; t += 32){
                float w = __expf(sAlpha[t] - m);
                sAlpha[t] = w;
                s += w;
            }
#pragma unroll
            for (int o = 16; o; o >>= 1)
                s += __shfl_xor_sync(0xffffffffu, s, o);
            float inv = 1.f / s;
            for (int t = beg + lane; t < end; t += 32)
                sAlpha[t] *= inv;
        }
        __syncthreads();

        // aggregation: pairwise edges (1 LDS.32 srcs + 1 LDS.64 alphas / 2 edges)
        {
            const int p = tid & 127;
            const int q = tid >> 7;
            const float2* sB2 = reinterpret_cast<const float2*>(sB);
            float2 bbv = reinterpret_cast<const float2*>(bb)[p];
            for (int dd = q*26; dd < q*26 + 26; dd++){
                int beg = sOff[dd], end = sOff[dd+1];
                unsigned long long acc = 0ull;
                int t = beg;
                if (t & 1){
                    int src = sSrc[t];
                    float al = sAlpha[t];
                    F2U xv; xv.f = sB2[src*(FD/2) + p];
                    fma2(acc, xv.u, pack2(al, al));
                    t++;
                }
#pragma unroll 2
                for (; t + 1 < end; t += 2){
                    int spair = *reinterpret_cast<const int*>(&sSrc[t]);
                    int s0 = spair & 0xffff;
                    int s1 = (spair >> 16) & 0xffff;
                    float2 al2 = *reinterpret_cast<const float2*>(&sAlpha[t]);
                    F2U x0; x0.f = sB2[s0*(FD/2) + p];
                    F2U x1; x1.f = sB2[s1*(FD/2) + p];
                    fma2(acc, x0.u, pack2(al2.x, al2.x));
                    fma2(acc, x1.u, pack2(al2.y, al2.y));
                }
                if (t < end){
                    int src = sSrc[t];
                    float al = sAlpha[t];
                    F2U xv; xv.f = sB2[src*(FD/2) + p];
                    fma2(acc, xv.u, pack2(al, al));
                }
                float2 r = unpack2(acc);
                float v0 = r.x + bbv.x;
                float v1 = r.y + bbv.y;
                int a0 = (dd >> 1)*512 + 4*p + (dd & 1);
                if (rnd == 1){
                    v0 = fmaxf(v0 + sA[a0],     0.f);
                    v1 = fmaxf(v1 + sA[a0 + 2], 0.f);
                }
                sA[a0]     = v0;
                sA[a0 + 2] = v1;
            }
        }
        __syncthreads();
    }

    // ---------------- channel attention (thread = column) ----------------
    {
        const int j = tid;
        float s = 0.f, m = -3.0e38f;
#pragma unroll 4
        for (int r = 0; r < NN; r++){
            float v = sA[paddr(r, j)];
            s += v; m = fmaxf(m, v);
        }
        sAvg[j] = s * (1.f/52.f);
        sMx[j]  = m;
    }
    __syncthreads();
    {
        const int j = tid;
        float aA = 0.f, aM = 0.f;
        const float* wc = Wm + j;
#pragma unroll 4
        for (int k = 0; k < FD; k++){
            float w = wc[k*FD];
            aA += sAvg[k]*w;
            aM += sMx[k]*w;
        }
        float bj = bm[j];
        float mval = sigmoidf_(fmaxf(aA + bj, 0.f) + fmaxf(aM + bj, 0.f));
        __syncthreads();     // sAvg/sMx reads complete before sMch write zone reuse
        sMch[j] = mval;
    }
    __syncthreads();

    // ---------------- node attention ----------------
    for (int r = wrp; r < NN; r += 8){
        float mx = -3.0e38f;
#pragma unroll
        for (int t = 0; t < 8; t++){
            int f = lane + 32*t;
            mx = fmaxf(mx, sA[paddr(r, f)] * sMch[f]);
        }
#pragma unroll
        for (int o = 16; o; o >>= 1)
            mx = fmaxf(mx, __shfl_down_sync(0xffffffffu, mx, o));
        if (lane == 0) sHmax[r] = mx;
    }
    __syncthreads();
    if (tid < NN){
        float s = 0.f;
        int beg = sOff[tid], end = sOff[tid+1];
        for (int t = beg; t < end; t++){
            int ss = sSrc[t];
            s += sDinv[ss] * sHmax[ss];
        }
        float aggv = sDinv[tid] * s * wgp[0] + bgp[0];
        sMno[tid] = sigmoidf_(aggv);
    }
    __syncthreads();

    // ---------------- final write (f = tid invariant; mch hoisted) ----------------
    {
        float* op = outg + (size_t)g*NN*FD + tid;
        float mch = sMch[tid];
        const float* ap = sA + 2*tid;
#pragma unroll 4
        for (int r = 0; r < NN; r++){
            op[r*FD] = ap[(r >> 1)*512 + (r & 1)] * mch * sMno[r];
        }
    }
}

extern "C" void kernel_launch(void* const* d_in, const int* in_sizes, int n_in,
                              void* d_out, int out_size)
{
    const float* x   = (const float*)d_in[0];
    const void*  ei  = d_in[1];
    const float* W0  = (const float*)d_in[2];
    const float* as0 = (const float*)d_in[3];
    const float* ad0 = (const float*)d_in[4];
    const float* b0  = (const float*)d_in[5];
    const float* W1  = (const float*)d_in[6];
    const float* as1 = (const float*)d_in[7];
    const float* ad1 = (const float*)d_in[8];
    const float* b1  = (const float*)d_in[9];
    const float* Wm  = (const float*)d_in[10];
    const float* bm  = (const float*)d_in[11];
    const float* wg  = (const float*)d_in[12];
    const float* bg  = (const float*)d_in[13];
    float* out = (float*)d_out;

    int B = in_sizes[0] / (NN*FD);

    cudaFuncSetAttribute(gcab_kernel,
                         cudaFuncAttributeMaxDynamicSharedMemorySize,
                         SMEM_BYTES);
    gcab_kernel<<<B, NT, SMEM_BYTES>>>(x, ei, W0, as0, ad0, b0,
                                       W1, as1, ad1, b1, Wm, bm, wg, bg, out);
}